// round 15
// baseline (speedup 1.0000x reference)
#include <cuda_runtime.h>
#include <cuda_fp16.h>
#include <mma.h>
#include <cstdint>

using namespace nvcuda;

#define N_NODES 50000
#define N_EDGES 800000
#define F 128
#define GRM 128                 // rows per GEMM block
#define LDA 136                 // padded leading dim (halves)
#define LDC 132                 // padded leading dim (floats) for C tile
#define CH 256
#define NCH ((N_NODES + CH - 1) / CH)   // 196
#define SMEM_GEMM (2 * GRM * LDA * 2)   // A + B tiles: 69632 B
// chunk split (GRM-aligned)
#define NODES_A 25088
#define NB_GEMM_A (NODES_A / GRM)                      // 196
#define NB_GEMM_B ((N_NODES - NODES_A + GRM - 1) / GRM) // 195
#define NB_GEMM_TOTAL (NB_GEMM_A + NB_GEMM_B)          // 391

// ---- scratch (no allocation allowed -> __device__ globals) ----
__device__ int    g_deg_src[N_NODES];
__device__ int    g_deg_dst[N_NODES];
__device__ float  g_out_norm[N_NODES];
__device__ float  g_in_norm[N_NODES];
__device__ int    g_row_ptr[N_NODES + 1];
__device__ int    g_cursor[N_NODES];
__device__ int    g_col_idx[N_EDGES];
__device__ int    g_chunk_sum[NCH];
__device__ float  g_c[N_NODES];        // c[s] = sum_{e: src=s} in_norm[dst_e]
__device__ __half g_x0[N_NODES * F];
__device__ __half g_x1[N_NODES * F];
__device__ __half g_m[N_NODES * F];
__device__ __half g_w1h[F * F];
__device__ __half g_w2h[F * F];
__device__ float  g_vec[F];
__device__ int    g_done;

// ---------------- setup ----------------
__global__ void k_count(const int* __restrict__ src, const int* __restrict__ dst,
                        const float* __restrict__ W1, const float* __restrict__ W2) {
    int i = blockIdx.x * blockDim.x + threadIdx.x;
    if (i < N_EDGES) {
        atomicAdd(&g_deg_src[src[i]], 1);
        atomicAdd(&g_deg_dst[dst[i]], 1);
    }
    if (i < F * F) {
        g_w1h[i] = __float2half(W1[i]);
        g_w2h[i] = __float2half(W2[i]);
    }
}

__global__ void k_scan1() {
    __shared__ int s[CH];
    int t = threadIdx.x;
    int i = blockIdx.x * CH + t;
    int v = (i < N_NODES) ? g_deg_dst[i] : 0;
    s[t] = v;
    __syncthreads();
    for (int off = 1; off < CH; off <<= 1) {
        int x = 0;
        if (t >= off) x = s[t - off];
        __syncthreads();
        if (t >= off) s[t] += x;
        __syncthreads();
    }
    if (i < N_NODES) g_row_ptr[i + 1] = s[t];
    if (t == CH - 1) g_chunk_sum[blockIdx.x] = s[t];
}

__global__ void k_scan23() {
    __shared__ int s[CH];
    int t = threadIdx.x;
    int bid = blockIdx.x;
    int v = (t < NCH) ? g_chunk_sum[t] : 0;
    s[t] = v;
    __syncthreads();
    for (int off = 1; off < CH; off <<= 1) {
        int x = 0;
        if (t >= off) x = s[t - off];
        __syncthreads();
        if (t >= off) s[t] += x;
        __syncthreads();
    }
    int chunk_off = (bid > 0) ? s[bid - 1] : 0;
    int i = bid * CH + t;
    if (i < N_NODES) {
        int rp = g_row_ptr[i + 1] + chunk_off;
        g_row_ptr[i + 1] = rp;
        int d = g_deg_dst[i];
        g_cursor[i] = rp - d;
        g_in_norm[i]  = rsqrtf((float)max(d, 1));
        g_out_norm[i] = rsqrtf((float)max(g_deg_src[i], 1));
        if (i == 0) g_row_ptr[0] = 0;
    }
}

// CSR fill (1 edge/thread) + c[s] + deg re-zero
__global__ void k_fill(const int* __restrict__ src, const int* __restrict__ dst) {
    int i = blockIdx.x * blockDim.x + threadIdx.x;
    if (i < N_NODES) { g_deg_src[i] = 0; g_deg_dst[i] = 0; }
    if (i < N_EDGES) {
        int s = src[i], d = dst[i];
        float in = g_in_norm[d];
        int p = atomicAdd(&g_cursor[d], 1);
        g_col_idx[p] = s;
        atomicAdd(&g_c[s], in);
    }
}

// feat -> fp16 prescaled (concurrent on stream 2)
__global__ void k_prep(const float* __restrict__ feat) {
    int i = blockIdx.x * blockDim.x + threadIdx.x;
    if (i < N_NODES * F / 4) {
        int base = i * 4;
        float on = g_out_norm[base >> 7];
        float4 v = *(const float4*)&feat[base];
        __half2 h01 = __floats2half2_rn(v.x * on, v.y * on);
        __half2 h23 = __floats2half2_rn(v.z * on, v.w * on);
        uint2 pk;
        pk.x = *(uint32_t*)&h01;
        pk.y = *(uint32_t*)&h23;
        *(uint2*)&g_x0[base] = pk;
    }
}

// ---------------- gather: warp per node (chunked), 16-lane halves ----------------
__global__ void __launch_bounds__(256)
k_agg(const __half* __restrict__ x, __half* __restrict__ m, int node0, int node1) {
    int w = node0 + ((blockIdx.x * blockDim.x + threadIdx.x) >> 5);
    int lane = threadIdx.x & 31;
    if (w >= node1) return;
    int half = lane >> 4, sl = lane & 15;
    const uint4* x4 = (const uint4*)x;
    const int* __restrict__ ci = g_col_idx;
    int beg = g_row_ptr[w], end = g_row_ptr[w + 1];
    float acc[8] = {0.f, 0.f, 0.f, 0.f, 0.f, 0.f, 0.f, 0.f};
    int e = beg;
    for (; e + 8 <= end; e += 8) {
        uint4 v0 = x4[ci[e + 0 + half] * 16 + sl];
        uint4 v1 = x4[ci[e + 2 + half] * 16 + sl];
        uint4 v2 = x4[ci[e + 4 + half] * 16 + sl];
        uint4 v3 = x4[ci[e + 6 + half] * 16 + sl];
        const __half2* h0 = (const __half2*)&v0;
        const __half2* h1 = (const __half2*)&v1;
        const __half2* h2 = (const __half2*)&v2;
        const __half2* h3 = (const __half2*)&v3;
#pragma unroll
        for (int k = 0; k < 4; k++) {
            __half2 s01 = __hadd2(h0[k], h1[k]);
            __half2 s23 = __hadd2(h2[k], h3[k]);
            __half2 s = __hadd2(s01, s23);
            float2 f = __half22float2(s);
            acc[2 * k]     += f.x;
            acc[2 * k + 1] += f.y;
        }
    }
    for (; e < end; e += 2) {
        int ee = e + half;
        if (ee < end) {
            uint4 v = x4[ci[ee] * 16 + sl];
            const __half2* h = (const __half2*)&v;
#pragma unroll
            for (int k = 0; k < 4; k++) {
                float2 f = __half22float2(h[k]);
                acc[2 * k]     += f.x;
                acc[2 * k + 1] += f.y;
            }
        }
    }
#pragma unroll
    for (int k = 0; k < 8; k++)
        acc[k] += __shfl_xor_sync(0xFFFFFFFFu, acc[k], 16);
    if (half == 0) {
        float sc = g_in_norm[w];
        __half2 h[4];
#pragma unroll
        for (int k = 0; k < 4; k++)
            h[k] = __floats2half2_rn(acc[2 * k] * sc, acc[2 * k + 1] * sc);
        ((uint4*)m)[w * 16 + sl] = *(uint4*)h;
    }
}

// ---------------- GEMM: m @ W + b -> relu -> *out_norm (chunked) ----------------
template<bool FOLD>
__global__ void __launch_bounds__(256, 2)
k_gemm(const __half* __restrict__ m, const __half* __restrict__ wh,
       const float* __restrict__ b, __half* __restrict__ y,
       const float* __restrict__ W3, const float* __restrict__ b3,
       float* __restrict__ out, int row_base) {
    extern __shared__ char smem[];
    __half* sA = (__half*)smem;                        // [128][LDA]
    __half* sB = (__half*)(smem + GRM * LDA * 2);      // [128][LDA]
    int t = threadIdx.x, warp = t >> 5, lane = t & 31;
    int row0 = row_base + blockIdx.x * GRM;

    {
        const uint4* asrc = (const uint4*)(m + (size_t)row0 * F);
        const uint4* bsrc = (const uint4*)wh;
        for (int i = t; i < GRM * 16; i += 256) {
            int r = i >> 4, c = i & 15;
            uint4 av = {0u, 0u, 0u, 0u};
            if (row0 + r < N_NODES) av = asrc[i];
            *(uint4*)&sA[r * LDA + c * 8] = av;
            *(uint4*)&sB[r * LDA + c * 8] = bsrc[i];
        }
    }
    __syncthreads();

    int wy = warp >> 1, wx = warp & 1;
    wmma::fragment<wmma::accumulator, 16, 16, 16, float> c[2][4];
#pragma unroll
    for (int i = 0; i < 2; i++)
#pragma unroll
        for (int j = 0; j < 4; j++) wmma::fill_fragment(c[i][j], 0.f);

#pragma unroll
    for (int k0 = 0; k0 < F; k0 += 16) {
        wmma::fragment<wmma::matrix_a, 16, 16, 16, __half, wmma::row_major> af[2];
        wmma::fragment<wmma::matrix_b, 16, 16, 16, __half, wmma::row_major> bf[4];
#pragma unroll
        for (int i = 0; i < 2; i++)
            wmma::load_matrix_sync(af[i], &sA[(wy * 32 + i * 16) * LDA + k0], LDA);
#pragma unroll
        for (int j = 0; j < 4; j++)
            wmma::load_matrix_sync(bf[j], &sB[k0 * LDA + wx * 64 + j * 16], LDA);
#pragma unroll
        for (int i = 0; i < 2; i++)
#pragma unroll
            for (int j = 0; j < 4; j++)
                wmma::mma_sync(c[i][j], af[i], bf[j], c[i][j]);
    }
    __syncthreads();   // sA/sB dead from here

    if (FOLD) {
        float* sC = (float*)smem;                      // [128][LDC]
        float* cw = (float*)smem + GRM * LDC;          // [128] row weights
        float* pr = cw + GRM;                          // [256] partials
#pragma unroll
        for (int i = 0; i < 2; i++)
#pragma unroll
            for (int j = 0; j < 4; j++)
                wmma::store_matrix_sync(&sC[(wy * 32 + i * 16) * LDC + wx * 64 + j * 16],
                                        c[i][j], LDC, wmma::mem_row_major);
        if (t < GRM) {
            int grow = row0 + t;
            if (grow < N_NODES) {
                cw[t] = g_c[grow] * g_out_norm[grow];
                g_c[grow] = 0.f;
            } else {
                cw[t] = 0.f;
            }
        }
        __syncthreads();

        int col = t & 127, rh = t >> 7;
        float bb = b[col];
        float acc = 0.f;
#pragma unroll 8
        for (int r = rh * 64; r < rh * 64 + 64; r++)
            acc += fmaxf(sC[r * LDC + col] + bb, 0.f) * cw[r];
        pr[t] = acc;
        __syncthreads();
        if (t < F) atomicAdd(&g_vec[t], (pr[t] + pr[t + 128]) * (1.0f / N_NODES));
        __threadfence();
        __syncthreads();
        __shared__ int s_last;
        if (t == 0) s_last = (atomicAdd(&g_done, 1) == NB_GEMM_TOTAL - 1);
        __syncthreads();
        if (s_last) {
            __shared__ float sv[F];
            if (t < F) sv[t] = *((volatile float*)&g_vec[t]);
            __syncthreads();
            if (t < F) {
                float acc2 = b3[t];
#pragma unroll 8
                for (int k = 0; k < F; k++) acc2 += sv[k] * W3[k * F + t];
                out[t] = acc2;
                g_vec[t] = 0.f;
            }
            if (t == 0) g_done = 0;
        }
    } else {
        float* wscr = (float*)smem + warp * (16 * 20);
#pragma unroll
        for (int i = 0; i < 2; i++) {
#pragma unroll
            for (int j = 0; j < 4; j++) {
                wmma::store_matrix_sync(wscr, c[i][j], 20, wmma::mem_row_major);
                __syncwarp();
                if (lane < 16) {
                    int grow = row0 + wy * 32 + i * 16 + lane;
                    if (grow < N_NODES) {
                        float on = g_out_norm[grow];
                        const float* cr = &wscr[lane * 20];
                        __half2 hv[8];
#pragma unroll
                        for (int cc = 0; cc < 16; cc += 4) {
                            float4 bv = *(const float4*)&b[wx * 64 + j * 16 + cc];
                            float v0 = fmaxf(cr[cc]     + bv.x, 0.f) * on;
                            float v1 = fmaxf(cr[cc + 1] + bv.y, 0.f) * on;
                            float v2 = fmaxf(cr[cc + 2] + bv.z, 0.f) * on;
                            float v3 = fmaxf(cr[cc + 3] + bv.w, 0.f) * on;
                            hv[cc / 2]     = __floats2half2_rn(v0, v1);
                            hv[cc / 2 + 1] = __floats2half2_rn(v2, v3);
                        }
                        uint4* dstp = (uint4*)(y + (size_t)grow * F + wx * 64 + j * 16);
                        dstp[0] = *(uint4*)&hv[0];
                        dstp[1] = *(uint4*)&hv[4];
                    }
                }
                __syncwarp();
            }
        }
    }
}

extern "C" void kernel_launch(void* const* d_in, const int* in_sizes, int n_in,
                              void* d_out, int out_size) {
    const float* feat = (const float*)d_in[0];
    const float* W1   = (const float*)d_in[1];
    const float* b1   = (const float*)d_in[2];
    const float* W2   = (const float*)d_in[3];
    const float* b2   = (const float*)d_in[4];
    const float* W3   = (const float*)d_in[5];
    const float* b3   = (const float*)d_in[6];
    const int*   src  = (const int*)d_in[7];
    const int*   dst  = (const int*)d_in[8];
    float* out = (float*)d_out;

    cudaFuncSetAttribute(k_gemm<false>, cudaFuncAttributeMaxDynamicSharedMemorySize, SMEM_GEMM);
    cudaFuncSetAttribute(k_gemm<true>,  cudaFuncAttributeMaxDynamicSharedMemorySize, SMEM_GEMM);

    void *p0, *p1, *pm, *pw1, *pw2;
    cudaGetSymbolAddress(&p0, g_x0);
    cudaGetSymbolAddress(&p1, g_x1);
    cudaGetSymbolAddress(&pm, g_m);
    cudaGetSymbolAddress(&pw1, g_w1h);
    cudaGetSymbolAddress(&pw2, g_w2h);
    __half* x0 = (__half*)p0;
    __half* x1 = (__half*)p1;
    __half* mm = (__half*)pm;
    __half* w1h = (__half*)pw1;
    __half* w2h = (__half*)pw2;

    int nb_edge1 = (N_EDGES + 255) / 256;            // 3125
    int nb_prep  = (N_NODES * F / 4 + 255) / 256;    // 6250
    int nb_aggA  = (NODES_A * 32) / 256;             // 3136
    int nb_aggB  = ((N_NODES - NODES_A) * 32 + 255) / 256;  // 3114

    cudaStream_t s2;
    cudaStreamCreateWithFlags(&s2, cudaStreamNonBlocking);
    cudaEvent_t evF, evP, e1, e2, e3, e4;
    cudaEventCreateWithFlags(&evF, cudaEventDisableTiming);
    cudaEventCreateWithFlags(&evP, cudaEventDisableTiming);
    cudaEventCreateWithFlags(&e1, cudaEventDisableTiming);
    cudaEventCreateWithFlags(&e2, cudaEventDisableTiming);
    cudaEventCreateWithFlags(&e3, cudaEventDisableTiming);
    cudaEventCreateWithFlags(&e4, cudaEventDisableTiming);

    // setup
    k_count<<<nb_edge1, 256>>>(src, dst, W1, W2);
    k_scan1<<<NCH, CH>>>();
    k_scan23<<<NCH, CH>>>();
    cudaEventRecord(evF, 0);
    cudaStreamWaitEvent(s2, evF, 0);
    k_fill<<<nb_edge1, 256>>>(src, dst);             // stream 0 (#4 profiled)
    k_prep<<<nb_prep, 256, 0, s2>>>(feat);           // concurrent
    cudaEventRecord(evP, s2);
    cudaStreamWaitEvent(0, evP, 0);

    // layer 1: aggA -> (gemmA on s2 || aggB on 0) -> gemmB on 0
    k_agg<<<nb_aggA, 256>>>(x0, mm, 0, NODES_A);
    cudaEventRecord(e1, 0);
    k_agg<<<nb_aggB, 256>>>(x0, mm, NODES_A, N_NODES);
    cudaStreamWaitEvent(s2, e1, 0);
    k_gemm<false><<<NB_GEMM_A, 256, SMEM_GEMM, s2>>>(mm, w1h, b1, x1, W3, b3, out, 0);
    cudaEventRecord(e2, s2);
    k_gemm<false><<<NB_GEMM_B, 256, SMEM_GEMM>>>(mm, w1h, b1, x1, W3, b3, out, NODES_A);
    cudaStreamWaitEvent(0, e2, 0);   // agg2 needs ALL of x1

    // layer 2 (FOLD): same pipeline
    k_agg<<<nb_aggA, 256>>>(x1, mm, 0, NODES_A);
    cudaEventRecord(e3, 0);
    k_agg<<<nb_aggB, 256>>>(x1, mm, NODES_A, N_NODES);
    cudaStreamWaitEvent(s2, e3, 0);
    k_gemm<true><<<NB_GEMM_A, 256, SMEM_GEMM, s2>>>(mm, w2h, b2, nullptr, W3, b3, out, 0);
    cudaEventRecord(e4, s2);
    k_gemm<true><<<NB_GEMM_B, 256, SMEM_GEMM>>>(mm, w2h, b2, nullptr, W3, b3, out, NODES_A);
    cudaStreamWaitEvent(0, e4, 0);   // join before harness reads out

    cudaEventDestroy(evF);
    cudaEventDestroy(evP);
    cudaEventDestroy(e1);
    cudaEventDestroy(e2);
    cudaEventDestroy(e3);
    cudaEventDestroy(e4);
    cudaStreamDestroy(s2);
}

// round 16
// speedup vs baseline: 1.3373x; 1.3373x over previous
#include <cuda_runtime.h>
#include <cuda_fp16.h>
#include <mma.h>
#include <cstdint>

using namespace nvcuda;

#define N_NODES 50000
#define N_EDGES 800000
#define F 128
#define GRM 128                 // rows per GEMM block
#define LDA 136                 // padded leading dim (halves)
#define LDC 132                 // padded leading dim (floats) for C tile
#define CH 256
#define NCH ((N_NODES + CH - 1) / CH)   // 196
#define SMEM_GEMM (2 * GRM * LDA * 2)   // A + B tiles: 69632 B

// ---- scratch (no allocation allowed -> __device__ globals) ----
// deg arrays re-zeroed in k_fill; g_c reset by owning FOLD-gemm block;
// g_vec/g_done reset by FOLD-gemm's last block. Module zero-init covers run 1.
__device__ int    g_deg_src[N_NODES];
__device__ int    g_deg_dst[N_NODES];
__device__ float  g_out_norm[N_NODES];
__device__ float  g_in_norm[N_NODES];
__device__ int    g_row_ptr[N_NODES + 1];
__device__ int    g_cursor[N_NODES];
__device__ int    g_col_idx[N_EDGES];
__device__ int    g_chunk_sum[NCH];
__device__ float  g_c[N_NODES];        // c[s] = sum_{e: src=s} in_norm[dst_e]
__device__ __half g_x0[N_NODES * F];
__device__ __half g_x1[N_NODES * F];
__device__ __half g_m[N_NODES * F];
__device__ __half g_w1h[F * F];
__device__ __half g_w2h[F * F];
__device__ float  g_vec[F];
__device__ int    g_done;

// ---------------- setup ----------------
__global__ void k_count(const int* __restrict__ src, const int* __restrict__ dst,
                        const float* __restrict__ W1, const float* __restrict__ W2) {
    int i = blockIdx.x * blockDim.x + threadIdx.x;
    if (i < N_EDGES) {
        atomicAdd(&g_deg_src[src[i]], 1);
        atomicAdd(&g_deg_dst[dst[i]], 1);
    }
    if (i < F * F) {
        g_w1h[i] = __float2half(W1[i]);
        g_w2h[i] = __float2half(W2[i]);
    }
}

__global__ void k_scan1() {
    __shared__ int s[CH];
    int t = threadIdx.x;
    int i = blockIdx.x * CH + t;
    int v = (i < N_NODES) ? g_deg_dst[i] : 0;
    s[t] = v;
    __syncthreads();
    for (int off = 1; off < CH; off <<= 1) {
        int x = 0;
        if (t >= off) x = s[t - off];
        __syncthreads();
        if (t >= off) s[t] += x;
        __syncthreads();
    }
    if (i < N_NODES) g_row_ptr[i + 1] = s[t];
    if (t == CH - 1) g_chunk_sum[blockIdx.x] = s[t];
}

__global__ void k_scan23() {
    __shared__ int s[CH];
    int t = threadIdx.x;
    int bid = blockIdx.x;
    int v = (t < NCH) ? g_chunk_sum[t] : 0;
    s[t] = v;
    __syncthreads();
    for (int off = 1; off < CH; off <<= 1) {
        int x = 0;
        if (t >= off) x = s[t - off];
        __syncthreads();
        if (t >= off) s[t] += x;
        __syncthreads();
    }
    int chunk_off = (bid > 0) ? s[bid - 1] : 0;
    int i = bid * CH + t;
    if (i < N_NODES) {
        int rp = g_row_ptr[i + 1] + chunk_off;
        g_row_ptr[i + 1] = rp;
        int d = g_deg_dst[i];
        g_cursor[i] = rp - d;
        g_in_norm[i]  = rsqrtf((float)max(d, 1));
        g_out_norm[i] = rsqrtf((float)max(g_deg_src[i], 1));
        if (i == 0) g_row_ptr[0] = 0;
    }
}

// CSR fill: 1 edge/thread + deg re-zero (g_c accumulation moved to k_c on s2)
__global__ void k_fill(const int* __restrict__ src, const int* __restrict__ dst) {
    int i = blockIdx.x * blockDim.x + threadIdx.x;
    if (i < N_NODES) { g_deg_src[i] = 0; g_deg_dst[i] = 0; }
    if (i < N_EDGES) {
        int s = src[i], d = dst[i];
        int p = atomicAdd(&g_cursor[d], 1);
        g_col_idx[p] = s;
    }
}

// feat -> fp16 prescaled (concurrent on stream 2)
__global__ void k_prep(const float* __restrict__ feat) {
    int i = blockIdx.x * blockDim.x + threadIdx.x;
    if (i < N_NODES * F / 4) {
        int base = i * 4;
        float on = g_out_norm[base >> 7];
        float4 v = *(const float4*)&feat[base];
        __half2 h01 = __floats2half2_rn(v.x * on, v.y * on);
        __half2 h23 = __floats2half2_rn(v.z * on, v.w * on);
        uint2 pk;
        pk.x = *(uint32_t*)&h01;
        pk.y = *(uint32_t*)&h23;
        *(uint2*)&g_x0[base] = pk;
    }
}

// c[s] accumulation (concurrent on stream 2, after k_prep; overlaps k_fill)
__global__ void k_c(const int* __restrict__ src, const int* __restrict__ dst) {
    int i = blockIdx.x * blockDim.x + threadIdx.x;
    if (i < N_EDGES)
        atomicAdd(&g_c[src[i]], g_in_norm[dst[i]]);
}

// ---------------- gather: warp per node, 2 edges/iter via 16-lane halves ----------------
__global__ void __launch_bounds__(256)
k_agg(const __half* __restrict__ x, __half* __restrict__ m) {
    int w = (blockIdx.x * blockDim.x + threadIdx.x) >> 5;
    int lane = threadIdx.x & 31;
    if (w >= N_NODES) return;
    int half = lane >> 4, sl = lane & 15;
    const uint4* x4 = (const uint4*)x;
    const int* __restrict__ ci = g_col_idx;
    int beg = g_row_ptr[w], end = g_row_ptr[w + 1];
    float acc[8] = {0.f, 0.f, 0.f, 0.f, 0.f, 0.f, 0.f, 0.f};
    int e = beg;
    for (; e + 8 <= end; e += 8) {
        uint4 v0 = x4[ci[e + 0 + half] * 16 + sl];
        uint4 v1 = x4[ci[e + 2 + half] * 16 + sl];
        uint4 v2 = x4[ci[e + 4 + half] * 16 + sl];
        uint4 v3 = x4[ci[e + 6 + half] * 16 + sl];
        const __half2* h0 = (const __half2*)&v0;
        const __half2* h1 = (const __half2*)&v1;
        const __half2* h2 = (const __half2*)&v2;
        const __half2* h3 = (const __half2*)&v3;
#pragma unroll
        for (int k = 0; k < 4; k++) {
            __half2 s01 = __hadd2(h0[k], h1[k]);
            __half2 s23 = __hadd2(h2[k], h3[k]);
            __half2 s = __hadd2(s01, s23);
            float2 f = __half22float2(s);
            acc[2 * k]     += f.x;
            acc[2 * k + 1] += f.y;
        }
    }
    for (; e < end; e += 2) {
        int ee = e + half;
        if (ee < end) {
            uint4 v = x4[ci[ee] * 16 + sl];
            const __half2* h = (const __half2*)&v;
#pragma unroll
            for (int k = 0; k < 4; k++) {
                float2 f = __half22float2(h[k]);
                acc[2 * k]     += f.x;
                acc[2 * k + 1] += f.y;
            }
        }
    }
#pragma unroll
    for (int k = 0; k < 8; k++)
        acc[k] += __shfl_xor_sync(0xFFFFFFFFu, acc[k], 16);
    if (half == 0) {
        float sc = g_in_norm[w];
        __half2 h[4];
#pragma unroll
        for (int k = 0; k < 4; k++)
            h[k] = __floats2half2_rn(acc[2 * k] * sc, acc[2 * k + 1] * sc);
        ((uint4*)m)[w * 16 + sl] = *(uint4*)h;
    }
}

// ---------------- GEMM: m @ W + b -> relu -> *out_norm ----------------
template<bool FOLD>
__global__ void __launch_bounds__(256, 2)
k_gemm(const __half* __restrict__ m, const __half* __restrict__ wh,
       const float* __restrict__ b, __half* __restrict__ y,
       const float* __restrict__ W3, const float* __restrict__ b3,
       float* __restrict__ out) {
    extern __shared__ char smem[];
    __half* sA = (__half*)smem;                        // [128][LDA]
    __half* sB = (__half*)(smem + GRM * LDA * 2);      // [128][LDA]
    int t = threadIdx.x, warp = t >> 5, lane = t & 31;
    int row0 = blockIdx.x * GRM;

    {
        const uint4* asrc = (const uint4*)(m + (size_t)row0 * F);
        const uint4* bsrc = (const uint4*)wh;
        for (int i = t; i < GRM * 16; i += 256) {
            int r = i >> 4, c = i & 15;
            uint4 av = {0u, 0u, 0u, 0u};
            if (row0 + r < N_NODES) av = asrc[i];
            *(uint4*)&sA[r * LDA + c * 8] = av;
            *(uint4*)&sB[r * LDA + c * 8] = bsrc[i];
        }
    }
    __syncthreads();

    int wy = warp >> 1, wx = warp & 1;
    wmma::fragment<wmma::accumulator, 16, 16, 16, float> c[2][4];
#pragma unroll
    for (int i = 0; i < 2; i++)
#pragma unroll
        for (int j = 0; j < 4; j++) wmma::fill_fragment(c[i][j], 0.f);

#pragma unroll
    for (int k0 = 0; k0 < F; k0 += 16) {
        wmma::fragment<wmma::matrix_a, 16, 16, 16, __half, wmma::row_major> af[2];
        wmma::fragment<wmma::matrix_b, 16, 16, 16, __half, wmma::row_major> bf[4];
#pragma unroll
        for (int i = 0; i < 2; i++)
            wmma::load_matrix_sync(af[i], &sA[(wy * 32 + i * 16) * LDA + k0], LDA);
#pragma unroll
        for (int j = 0; j < 4; j++)
            wmma::load_matrix_sync(bf[j], &sB[k0 * LDA + wx * 64 + j * 16], LDA);
#pragma unroll
        for (int i = 0; i < 2; i++)
#pragma unroll
            for (int j = 0; j < 4; j++)
                wmma::mma_sync(c[i][j], af[i], bf[j], c[i][j]);
    }
    __syncthreads();   // sA/sB dead from here

    if (FOLD) {
        float* sC = (float*)smem;                      // [128][LDC]
        float* cw = (float*)smem + GRM * LDC;          // [128] row weights
        float* pr = cw + GRM;                          // [256] partials
#pragma unroll
        for (int i = 0; i < 2; i++)
#pragma unroll
            for (int j = 0; j < 4; j++)
                wmma::store_matrix_sync(&sC[(wy * 32 + i * 16) * LDC + wx * 64 + j * 16],
                                        c[i][j], LDC, wmma::mem_row_major);
        if (t < GRM) {
            int grow = row0 + t;
            if (grow < N_NODES) {
                cw[t] = g_c[grow] * g_out_norm[grow];
                g_c[grow] = 0.f;
            } else {
                cw[t] = 0.f;
            }
        }
        __syncthreads();

        int col = t & 127, rh = t >> 7;
        float bb = b[col];
        float acc = 0.f;
#pragma unroll 8
        for (int r = rh * 64; r < rh * 64 + 64; r++)
            acc += fmaxf(sC[r * LDC + col] + bb, 0.f) * cw[r];
        pr[t] = acc;
        __syncthreads();
        if (t < F) atomicAdd(&g_vec[t], (pr[t] + pr[t + 128]) * (1.0f / N_NODES));
        __threadfence();
        __syncthreads();
        __shared__ int s_last;
        if (t == 0) s_last = (atomicAdd(&g_done, 1) == (int)gridDim.x - 1);
        __syncthreads();
        if (s_last) {
            __shared__ float sv[F];
            if (t < F) sv[t] = *((volatile float*)&g_vec[t]);
            __syncthreads();
            if (t < F) {
                float acc2 = b3[t];
#pragma unroll 8
                for (int k = 0; k < F; k++) acc2 += sv[k] * W3[k * F + t];
                out[t] = acc2;
                g_vec[t] = 0.f;
            }
            if (t == 0) g_done = 0;
        }
    } else {
        float* wscr = (float*)smem + warp * (16 * 20);
#pragma unroll
        for (int i = 0; i < 2; i++) {
#pragma unroll
            for (int j = 0; j < 4; j++) {
                wmma::store_matrix_sync(wscr, c[i][j], 20, wmma::mem_row_major);
                __syncwarp();
                if (lane < 16) {
                    int grow = row0 + wy * 32 + i * 16 + lane;
                    if (grow < N_NODES) {
                        float on = g_out_norm[grow];
                        const float* cr = &wscr[lane * 20];
                        __half2 hv[8];
#pragma unroll
                        for (int cc = 0; cc < 16; cc += 4) {
                            float4 bv = *(const float4*)&b[wx * 64 + j * 16 + cc];
                            float v0 = fmaxf(cr[cc]     + bv.x, 0.f) * on;
                            float v1 = fmaxf(cr[cc + 1] + bv.y, 0.f) * on;
                            float v2 = fmaxf(cr[cc + 2] + bv.z, 0.f) * on;
                            float v3 = fmaxf(cr[cc + 3] + bv.w, 0.f) * on;
                            hv[cc / 2]     = __floats2half2_rn(v0, v1);
                            hv[cc / 2 + 1] = __floats2half2_rn(v2, v3);
                        }
                        uint4* dstp = (uint4*)(y + (size_t)grow * F + wx * 64 + j * 16);
                        dstp[0] = *(uint4*)&hv[0];
                        dstp[1] = *(uint4*)&hv[4];
                    }
                }
                __syncwarp();
            }
        }
    }
}

extern "C" void kernel_launch(void* const* d_in, const int* in_sizes, int n_in,
                              void* d_out, int out_size) {
    const float* feat = (const float*)d_in[0];
    const float* W1   = (const float*)d_in[1];
    const float* b1   = (const float*)d_in[2];
    const float* W2   = (const float*)d_in[3];
    const float* b2   = (const float*)d_in[4];
    const float* W3   = (const float*)d_in[5];
    const float* b3   = (const float*)d_in[6];
    const int*   src  = (const int*)d_in[7];
    const int*   dst  = (const int*)d_in[8];
    float* out = (float*)d_out;

    cudaFuncSetAttribute(k_gemm<false>, cudaFuncAttributeMaxDynamicSharedMemorySize, SMEM_GEMM);
    cudaFuncSetAttribute(k_gemm<true>,  cudaFuncAttributeMaxDynamicSharedMemorySize, SMEM_GEMM);

    void *p0, *p1, *pm, *pw1, *pw2;
    cudaGetSymbolAddress(&p0, g_x0);
    cudaGetSymbolAddress(&p1, g_x1);
    cudaGetSymbolAddress(&pm, g_m);
    cudaGetSymbolAddress(&pw1, g_w1h);
    cudaGetSymbolAddress(&pw2, g_w2h);
    __half* x0 = (__half*)p0;
    __half* x1 = (__half*)p1;
    __half* mm = (__half*)pm;
    __half* w1h = (__half*)pw1;
    __half* w2h = (__half*)pw2;

    int nb_edge1 = (N_EDGES + 255) / 256;            // 3125
    int nb_aggw  = (N_NODES * 32 + 255) / 256;       // 6250
    int nb_gemm  = (N_NODES + GRM - 1) / GRM;        // 391
    int nb_prep  = (N_NODES * F / 4 + 255) / 256;    // 6250

    cudaStream_t s2;
    cudaEvent_t ev_fork, ev_join;
    cudaStreamCreateWithFlags(&s2, cudaStreamNonBlocking);
    cudaEventCreateWithFlags(&ev_fork, cudaEventDisableTiming);
    cudaEventCreateWithFlags(&ev_join, cudaEventDisableTiming);

    k_count<<<nb_edge1, 256>>>(src, dst, W1, W2);
    k_scan1<<<NCH, CH>>>();
    k_scan23<<<NCH, CH>>>();
    cudaEventRecord(ev_fork, 0);
    cudaStreamWaitEvent(s2, ev_fork, 0);
    k_fill<<<nb_edge1, 256>>>(src, dst);             // stream 0 (#4 profiled)
    k_prep<<<nb_prep, 256, 0, s2>>>(feat);           // concurrent: DRAM-bound
    k_c<<<nb_edge1, 256, 0, s2>>>(src, dst);         // concurrent: g_c atomics
    cudaEventRecord(ev_join, s2);
    cudaStreamWaitEvent(0, ev_join, 0);

    k_agg<<<nb_aggw, 256>>>(x0, mm);
    k_gemm<false><<<nb_gemm, 256, SMEM_GEMM>>>(mm, w1h, b1, x1, W3, b3, out);
    k_agg<<<nb_aggw, 256>>>(x1, mm);
    k_gemm<true><<<nb_gemm, 256, SMEM_GEMM>>>(mm, w2h, b2, nullptr, W3, b3, out);

    cudaEventDestroy(ev_fork);
    cudaEventDestroy(ev_join);
    cudaStreamDestroy(s2);
}

// round 17
// speedup vs baseline: 1.3454x; 1.0061x over previous
#include <cuda_runtime.h>
#include <cuda_fp16.h>
#include <mma.h>
#include <cstdint>

using namespace nvcuda;

#define N_NODES 50000
#define N_EDGES 800000
#define F 128
#define GRM 128                 // rows per GEMM block
#define LDA 136                 // padded leading dim (halves)
#define LDC 132                 // padded leading dim (floats) for C tile
#define CH 256
#define NCH ((N_NODES + CH - 1) / CH)   // 196
#define SMEM_GEMM (2 * GRM * LDA * 2)   // A + B tiles: 69632 B

// ---- scratch (no allocation allowed -> __device__ globals) ----
// deg arrays re-zeroed in k_fill; g_c reset by owning FOLD-gemm block;
// g_vec/g_done reset by FOLD-gemm's last block. Module zero-init covers run 1.
__device__ int    g_deg_src[N_NODES];
__device__ int    g_deg_dst[N_NODES];
__device__ float  g_out_norm[N_NODES];
__device__ float  g_in_norm[N_NODES];
__device__ int    g_row_ptr[N_NODES + 1];
__device__ int    g_cursor[N_NODES];
__device__ int    g_col_idx[N_EDGES];
__device__ int    g_chunk_sum[NCH];
__device__ float  g_c[N_NODES];        // c[s] = sum_{e: src=s} in_norm[dst_e]
__device__ __half g_x0[N_NODES * F];
__device__ __half g_x1[N_NODES * F];
__device__ __half g_m[N_NODES * F];
__device__ __half g_w1h[F * F];
__device__ __half g_w2h[F * F];
__device__ float  g_vec[F];
__device__ int    g_done;

// ---------------- setup ----------------
__global__ void k_count(const int* __restrict__ src, const int* __restrict__ dst,
                        const float* __restrict__ W1, const float* __restrict__ W2) {
    int i = blockIdx.x * blockDim.x + threadIdx.x;
    if (i < N_EDGES) {
        atomicAdd(&g_deg_src[src[i]], 1);
        atomicAdd(&g_deg_dst[dst[i]], 1);
    }
    if (i < F * F) {
        g_w1h[i] = __float2half(W1[i]);
        g_w2h[i] = __float2half(W2[i]);
    }
}

__global__ void k_scan1() {
    __shared__ int s[CH];
    int t = threadIdx.x;
    int i = blockIdx.x * CH + t;
    int v = (i < N_NODES) ? g_deg_dst[i] : 0;
    s[t] = v;
    __syncthreads();
    for (int off = 1; off < CH; off <<= 1) {
        int x = 0;
        if (t >= off) x = s[t - off];
        __syncthreads();
        if (t >= off) s[t] += x;
        __syncthreads();
    }
    if (i < N_NODES) g_row_ptr[i + 1] = s[t];
    if (t == CH - 1) g_chunk_sum[blockIdx.x] = s[t];
}

__global__ void k_scan23() {
    __shared__ int s[CH];
    int t = threadIdx.x;
    int bid = blockIdx.x;
    int v = (t < NCH) ? g_chunk_sum[t] : 0;
    s[t] = v;
    __syncthreads();
    for (int off = 1; off < CH; off <<= 1) {
        int x = 0;
        if (t >= off) x = s[t - off];
        __syncthreads();
        if (t >= off) s[t] += x;
        __syncthreads();
    }
    int chunk_off = (bid > 0) ? s[bid - 1] : 0;
    int i = bid * CH + t;
    if (i < N_NODES) {
        int rp = g_row_ptr[i + 1] + chunk_off;
        g_row_ptr[i + 1] = rp;
        int d = g_deg_dst[i];
        g_cursor[i] = rp - d;
        g_in_norm[i]  = rsqrtf((float)max(d, 1));
        g_out_norm[i] = rsqrtf((float)max(g_deg_src[i], 1));
        if (i == 0) g_row_ptr[0] = 0;
    }
}

// CSR fill: 1 edge/thread + deg re-zero
__global__ void k_fill(const int* __restrict__ src, const int* __restrict__ dst) {
    int i = blockIdx.x * blockDim.x + threadIdx.x;
    if (i < N_NODES) { g_deg_src[i] = 0; g_deg_dst[i] = 0; }
    if (i < N_EDGES) {
        int s = src[i], d = dst[i];
        int p = atomicAdd(&g_cursor[d], 1);
        g_col_idx[p] = s;
    }
}

// feat -> fp16 prescaled (s2, hidden under k_fill)
__global__ void k_prep(const float* __restrict__ feat) {
    int i = blockIdx.x * blockDim.x + threadIdx.x;
    if (i < N_NODES * F / 4) {
        int base = i * 4;
        float on = g_out_norm[base >> 7];
        float4 v = *(const float4*)&feat[base];
        __half2 h01 = __floats2half2_rn(v.x * on, v.y * on);
        __half2 h23 = __floats2half2_rn(v.z * on, v.w * on);
        uint2 pk;
        pk.x = *(uint32_t*)&h01;
        pk.y = *(uint32_t*)&h23;
        *(uint2*)&g_x0[base] = pk;
    }
}

// c[s] accumulation (s2, hidden under layer-1 GEMM; only needed by FOLD gemm)
__global__ void k_c(const int* __restrict__ src, const int* __restrict__ dst) {
    int i = blockIdx.x * blockDim.x + threadIdx.x;
    if (i < N_EDGES)
        atomicAdd(&g_c[src[i]], g_in_norm[dst[i]]);
}

// ---------------- gather: warp per node, 2 edges/iter via 16-lane halves ----------------
__global__ void __launch_bounds__(256)
k_agg(const __half* __restrict__ x, __half* __restrict__ m) {
    int w = (blockIdx.x * blockDim.x + threadIdx.x) >> 5;
    int lane = threadIdx.x & 31;
    if (w >= N_NODES) return;
    int half = lane >> 4, sl = lane & 15;
    const uint4* x4 = (const uint4*)x;
    const int* __restrict__ ci = g_col_idx;
    int beg = g_row_ptr[w], end = g_row_ptr[w + 1];
    float acc[8] = {0.f, 0.f, 0.f, 0.f, 0.f, 0.f, 0.f, 0.f};
    int e = beg;
    for (; e + 8 <= end; e += 8) {
        uint4 v0 = x4[ci[e + 0 + half] * 16 + sl];
        uint4 v1 = x4[ci[e + 2 + half] * 16 + sl];
        uint4 v2 = x4[ci[e + 4 + half] * 16 + sl];
        uint4 v3 = x4[ci[e + 6 + half] * 16 + sl];
        const __half2* h0 = (const __half2*)&v0;
        const __half2* h1 = (const __half2*)&v1;
        const __half2* h2 = (const __half2*)&v2;
        const __half2* h3 = (const __half2*)&v3;
#pragma unroll
        for (int k = 0; k < 4; k++) {
            __half2 s01 = __hadd2(h0[k], h1[k]);
            __half2 s23 = __hadd2(h2[k], h3[k]);
            __half2 s = __hadd2(s01, s23);
            float2 f = __half22float2(s);
            acc[2 * k]     += f.x;
            acc[2 * k + 1] += f.y;
        }
    }
    for (; e < end; e += 2) {
        int ee = e + half;
        if (ee < end) {
            uint4 v = x4[ci[ee] * 16 + sl];
            const __half2* h = (const __half2*)&v;
#pragma unroll
            for (int k = 0; k < 4; k++) {
                float2 f = __half22float2(h[k]);
                acc[2 * k]     += f.x;
                acc[2 * k + 1] += f.y;
            }
        }
    }
#pragma unroll
    for (int k = 0; k < 8; k++)
        acc[k] += __shfl_xor_sync(0xFFFFFFFFu, acc[k], 16);
    if (half == 0) {
        float sc = g_in_norm[w];
        __half2 h[4];
#pragma unroll
        for (int k = 0; k < 4; k++)
            h[k] = __floats2half2_rn(acc[2 * k] * sc, acc[2 * k + 1] * sc);
        ((uint4*)m)[w * 16 + sl] = *(uint4*)h;
    }
}

// ---------------- GEMM: m @ W + b -> relu -> *out_norm ----------------
template<bool FOLD>
__global__ void __launch_bounds__(256, 2)
k_gemm(const __half* __restrict__ m, const __half* __restrict__ wh,
       const float* __restrict__ b, __half* __restrict__ y,
       const float* __restrict__ W3, const float* __restrict__ b3,
       float* __restrict__ out) {
    extern __shared__ char smem[];
    __half* sA = (__half*)smem;                        // [128][LDA]
    __half* sB = (__half*)(smem + GRM * LDA * 2);      // [128][LDA]
    int t = threadIdx.x, warp = t >> 5, lane = t & 31;
    int row0 = blockIdx.x * GRM;

    {
        const uint4* asrc = (const uint4*)(m + (size_t)row0 * F);
        const uint4* bsrc = (const uint4*)wh;
        for (int i = t; i < GRM * 16; i += 256) {
            int r = i >> 4, c = i & 15;
            uint4 av = {0u, 0u, 0u, 0u};
            if (row0 + r < N_NODES) av = asrc[i];
            *(uint4*)&sA[r * LDA + c * 8] = av;
            *(uint4*)&sB[r * LDA + c * 8] = bsrc[i];
        }
    }
    __syncthreads();

    int wy = warp >> 1, wx = warp & 1;
    wmma::fragment<wmma::accumulator, 16, 16, 16, float> c[2][4];
#pragma unroll
    for (int i = 0; i < 2; i++)
#pragma unroll
        for (int j = 0; j < 4; j++) wmma::fill_fragment(c[i][j], 0.f);

#pragma unroll
    for (int k0 = 0; k0 < F; k0 += 16) {
        wmma::fragment<wmma::matrix_a, 16, 16, 16, __half, wmma::row_major> af[2];
        wmma::fragment<wmma::matrix_b, 16, 16, 16, __half, wmma::row_major> bf[4];
#pragma unroll
        for (int i = 0; i < 2; i++)
            wmma::load_matrix_sync(af[i], &sA[(wy * 32 + i * 16) * LDA + k0], LDA);
#pragma unroll
        for (int j = 0; j < 4; j++)
            wmma::load_matrix_sync(bf[j], &sB[k0 * LDA + wx * 64 + j * 16], LDA);
#pragma unroll
        for (int i = 0; i < 2; i++)
#pragma unroll
            for (int j = 0; j < 4; j++)
                wmma::mma_sync(c[i][j], af[i], bf[j], c[i][j]);
    }
    __syncthreads();   // sA/sB dead from here

    if (FOLD) {
        float* sC = (float*)smem;                      // [128][LDC]
        float* cw = (float*)smem + GRM * LDC;          // [128] row weights
        float* pr = cw + GRM;                          // [256] partials
#pragma unroll
        for (int i = 0; i < 2; i++)
#pragma unroll
            for (int j = 0; j < 4; j++)
                wmma::store_matrix_sync(&sC[(wy * 32 + i * 16) * LDC + wx * 64 + j * 16],
                                        c[i][j], LDC, wmma::mem_row_major);
        if (t < GRM) {
            int grow = row0 + t;
            if (grow < N_NODES) {
                cw[t] = g_c[grow] * g_out_norm[grow];
                g_c[grow] = 0.f;
            } else {
                cw[t] = 0.f;
            }
        }
        __syncthreads();

        int col = t & 127, rh = t >> 7;
        float bb = b[col];
        float acc = 0.f;
#pragma unroll 8
        for (int r = rh * 64; r < rh * 64 + 64; r++)
            acc += fmaxf(sC[r * LDC + col] + bb, 0.f) * cw[r];
        pr[t] = acc;
        __syncthreads();
        if (t < F) atomicAdd(&g_vec[t], (pr[t] + pr[t + 128]) * (1.0f / N_NODES));
        __threadfence();
        __syncthreads();
        __shared__ int s_last;
        if (t == 0) s_last = (atomicAdd(&g_done, 1) == (int)gridDim.x - 1);
        __syncthreads();
        if (s_last) {
            __shared__ float sv[F];
            if (t < F) sv[t] = *((volatile float*)&g_vec[t]);
            __syncthreads();
            if (t < F) {
                float acc2 = b3[t];
#pragma unroll 8
                for (int k = 0; k < F; k++) acc2 += sv[k] * W3[k * F + t];
                out[t] = acc2;
                g_vec[t] = 0.f;
            }
            if (t == 0) g_done = 0;
        }
    } else {
        float* wscr = (float*)smem + warp * (16 * 20);
#pragma unroll
        for (int i = 0; i < 2; i++) {
#pragma unroll
            for (int j = 0; j < 4; j++) {
                wmma::store_matrix_sync(wscr, c[i][j], 20, wmma::mem_row_major);
                __syncwarp();
                if (lane < 16) {
                    int grow = row0 + wy * 32 + i * 16 + lane;
                    if (grow < N_NODES) {
                        float on = g_out_norm[grow];
                        const float* cr = &wscr[lane * 20];
                        __half2 hv[8];
#pragma unroll
                        for (int cc = 0; cc < 16; cc += 4) {
                            float4 bv = *(const float4*)&b[wx * 64 + j * 16 + cc];
                            float v0 = fmaxf(cr[cc]     + bv.x, 0.f) * on;
                            float v1 = fmaxf(cr[cc + 1] + bv.y, 0.f) * on;
                            float v2 = fmaxf(cr[cc + 2] + bv.z, 0.f) * on;
                            float v3 = fmaxf(cr[cc + 3] + bv.w, 0.f) * on;
                            hv[cc / 2]     = __floats2half2_rn(v0, v1);
                            hv[cc / 2 + 1] = __floats2half2_rn(v2, v3);
                        }
                        uint4* dstp = (uint4*)(y + (size_t)grow * F + wx * 64 + j * 16);
                        dstp[0] = *(uint4*)&hv[0];
                        dstp[1] = *(uint4*)&hv[4];
                    }
                }
                __syncwarp();
            }
        }
    }
}

extern "C" void kernel_launch(void* const* d_in, const int* in_sizes, int n_in,
                              void* d_out, int out_size) {
    const float* feat = (const float*)d_in[0];
    const float* W1   = (const float*)d_in[1];
    const float* b1   = (const float*)d_in[2];
    const float* W2   = (const float*)d_in[3];
    const float* b2   = (const float*)d_in[4];
    const float* W3   = (const float*)d_in[5];
    const float* b3   = (const float*)d_in[6];
    const int*   src  = (const int*)d_in[7];
    const int*   dst  = (const int*)d_in[8];
    float* out = (float*)d_out;

    cudaFuncSetAttribute(k_gemm<false>, cudaFuncAttributeMaxDynamicSharedMemorySize, SMEM_GEMM);
    cudaFuncSetAttribute(k_gemm<true>,  cudaFuncAttributeMaxDynamicSharedMemorySize, SMEM_GEMM);

    void *p0, *p1, *pm, *pw1, *pw2;
    cudaGetSymbolAddress(&p0, g_x0);
    cudaGetSymbolAddress(&p1, g_x1);
    cudaGetSymbolAddress(&pm, g_m);
    cudaGetSymbolAddress(&pw1, g_w1h);
    cudaGetSymbolAddress(&pw2, g_w2h);
    __half* x0 = (__half*)p0;
    __half* x1 = (__half*)p1;
    __half* mm = (__half*)pm;
    __half* w1h = (__half*)pw1;
    __half* w2h = (__half*)pw2;

    int nb_edge1 = (N_EDGES + 255) / 256;            // 3125
    int nb_aggw  = (N_NODES * 32 + 255) / 256;       // 6250
    int nb_gemm  = (N_NODES + GRM - 1) / GRM;        // 391
    int nb_prep  = (N_NODES * F / 4 + 255) / 256;    // 6250

    cudaStream_t s2;
    cudaEvent_t ev_fork, ev_join, evA, evC;
    cudaStreamCreateWithFlags(&s2, cudaStreamNonBlocking);
    cudaEventCreateWithFlags(&ev_fork, cudaEventDisableTiming);
    cudaEventCreateWithFlags(&ev_join, cudaEventDisableTiming);
    cudaEventCreateWithFlags(&evA, cudaEventDisableTiming);
    cudaEventCreateWithFlags(&evC, cudaEventDisableTiming);

    // setup: count -> scans -> (fill || prep)
    k_count<<<nb_edge1, 256>>>(src, dst, W1, W2);
    k_scan1<<<NCH, CH>>>();
    k_scan23<<<NCH, CH>>>();
    cudaEventRecord(ev_fork, 0);
    cudaStreamWaitEvent(s2, ev_fork, 0);
    k_fill<<<nb_edge1, 256>>>(src, dst);             // stream 0 (#4 profiled)
    k_prep<<<nb_prep, 256, 0, s2>>>(feat);           // hidden under fill
    cudaEventRecord(ev_join, s2);
    cudaStreamWaitEvent(0, ev_join, 0);

    // layer 1; k_c overlaps gemm1 (tensor-bound) on s2
    k_agg<<<nb_aggw, 256>>>(x0, mm);
    cudaEventRecord(evA, 0);
    cudaStreamWaitEvent(s2, evA, 0);
    k_c<<<nb_edge1, 256, 0, s2>>>(src, dst);         // hidden under gemm1
    cudaEventRecord(evC, s2);
    k_gemm<false><<<nb_gemm, 256, SMEM_GEMM>>>(mm, w1h, b1, x1, W3, b3, out);

    // layer 2
    k_agg<<<nb_aggw, 256>>>(x1, mm);
    cudaStreamWaitEvent(0, evC, 0);                  // g_c ready before FOLD gemm
    k_gemm<true><<<nb_gemm, 256, SMEM_GEMM>>>(mm, w2h, b2, nullptr, W3, b3, out);

    cudaEventDestroy(ev_fork);
    cudaEventDestroy(ev_join);
    cudaEventDestroy(evA);
    cudaEventDestroy(evC);
    cudaStreamDestroy(s2);
}